// round 4
// baseline (speedup 1.0000x reference)
#include <cuda_runtime.h>
#include <cstdint>

#define Bn   8
#define CIn  512
#define COn  512
#define KSn  3
#define WDn  512
#define Hn   64
#define HPn  66
#define KTOT (CIn*KSn*KSn)   // 4608
#define HWn  (Hn*Hn)         // 4096

// ---------------- scratch (device globals; no allocations) ----------------
static __device__ float g_s[Bn*CIn];
static __device__ float g_demod[Bn*COn];
static __device__ float g_wt[(size_t)Bn*KTOT*COn];       // [b][citap][co]  (tf32-rounded)
static __device__ float g_xpad[(size_t)Bn*CIn*HPn*HPn];  // padded input    (tf32-rounded)

// ---------------- helpers ----------------
__device__ __forceinline__ float tf32r(float x) {
    unsigned u;
    asm("cvt.rna.tf32.f32 %0, %1;" : "=r"(u) : "f"(x));
    return __uint_as_float(u);
}

__device__ __forceinline__ void mma_tf32(float c[4], const uint32_t a[4], const uint32_t b2[2]) {
    asm volatile(
        "mma.sync.aligned.m16n8k8.row.col.f32.tf32.tf32.f32 "
        "{%0,%1,%2,%3},{%4,%5,%6,%7},{%8,%9},{%0,%1,%2,%3};\n"
        : "+f"(c[0]), "+f"(c[1]), "+f"(c[2]), "+f"(c[3])
        : "r"(a[0]), "r"(a[1]), "r"(a[2]), "r"(a[3]), "r"(b2[0]), "r"(b2[1]));
}

// ---------------- 1) style modulation: s[b,ci] = eq*style[b]·mw[ci] + mb[ci] ----------------
__global__ void k_style(const float* __restrict__ style,
                        const float* __restrict__ mw,
                        const float* __restrict__ mb) {
    const int b = blockIdx.x;
    const int ci = threadIdx.x;            // blockDim = 512
    __shared__ float st[WDn];
    st[ci] = style[b*WDn + ci];
    __syncthreads();
    const float eq = 0.044194173824159216f;  // 1/sqrt(512)
    const float* row = mw + (size_t)ci*WDn;
    float acc = 0.f;
    #pragma unroll 8
    for (int w = 0; w < WDn; w++) acc += st[w] * row[w];
    g_s[b*CIn + ci] = acc * eq + mb[ci];
}

// ---------------- 2) demod[b,co] = rsqrt(cs^2 * sum (w*s)^2 + 1e-8) ----------------
__global__ void k_demod(const float* __restrict__ weight) {
    const int bc = blockIdx.x;             // b*512 + co
    const int b = bc >> 9, co = bc & 511;
    const float* w = weight + (size_t)co*KTOT;
    const float* s = g_s + b*CIn;
    float acc = 0.f;
    for (int i = threadIdx.x; i < KTOT; i += 256) {
        float v = w[i] * s[i / 9];
        acc += v * v;
    }
    #pragma unroll
    for (int o = 16; o; o >>= 1) acc += __shfl_xor_sync(0xffffffffu, acc, o);
    __shared__ float red[8];
    if ((threadIdx.x & 31) == 0) red[threadIdx.x >> 5] = acc;
    __syncthreads();
    if (threadIdx.x == 0) {
        float t = 0.f;
        #pragma unroll
        for (int i = 0; i < 8; i++) t += red[i];
        const float cs2 = 1.0f / (float)KTOT;   // conv_scale^2
        g_demod[bc] = rsqrtf(cs2 * t + 1e-8f);
    }
}

// ---------------- 3) w_t[b][citap][co] = tf32( cs * weight[co][citap] * s[b][ci] * demod[b][co] ) ----------------
__global__ void k_wt(const float* __restrict__ weight) {
    __shared__ float tile[32][33];
    const int k0 = blockIdx.x * 32;        // citap
    const int c0 = blockIdx.y * 32;        // co
    const int b  = blockIdx.z;
    const int tx = threadIdx.x, ty = threadIdx.y;   // (32, 8)
    #pragma unroll
    for (int i = 0; i < 4; i++)
        tile[ty + 8*i][tx] = weight[(size_t)(c0 + ty + 8*i)*KTOT + k0 + tx];
    __syncthreads();
    const float CS = 0.014731391274719742f;  // 1/sqrt(4608)
    const float dm = g_demod[b*COn + c0 + tx];
    #pragma unroll
    for (int i = 0; i < 4; i++) {
        const int k = k0 + ty + 8*i;
        const int ci = k / 9;
        float v = CS * tile[tx][ty + 8*i] * g_s[b*CIn + ci] * dm;
        g_wt[((size_t)b*KTOT + k)*COn + c0 + tx] = tf32r(v);
    }
}

// ---------------- 4) zero-padded, tf32-rounded input ----------------
__global__ void k_pad(const float* __restrict__ x) {
    const int plane = blockIdx.x;          // b*CI + ci
    const float* src = x + (size_t)plane * HWn;
    float* dst = g_xpad + (size_t)plane * HPn * HPn;
    for (int i = threadIdx.x; i < HPn*HPn; i += blockDim.x) {
        const int y = i / HPn, xx = i % HPn;
        float v = 0.f;
        if (y >= 1 && y <= Hn && xx >= 1 && xx <= Hn)
            v = src[(y-1)*Hn + (xx-1)];
        dst[i] = tf32r(v);
    }
}

// ---------------- 5) implicit GEMM conv + fused epilogue ----------------
#define BM 128
#define BN 128
#define KT 16
#define LDSA 136   // stride pad -> conflict-free fragment reads

__global__ void __launch_bounds__(256) k_conv(const float* __restrict__ noise,
                                              const float* __restrict__ noise_w,
                                              const float* __restrict__ act_b,
                                              float* __restrict__ out) {
    __shared__ float As[2][KT*LDSA];
    __shared__ float Bs[2][KT*LDSA];

    const int tid  = threadIdx.x;
    const int lane = tid & 31, warp = tid >> 5;
    const int wm = warp & 1, wn = warp >> 1;            // 2 x 4 warps
    const int m0 = blockIdx.y * BM;                     // co tile
    const int n0 = blockIdx.x * BN;                     // hw tile (2 image rows)
    const int b  = blockIdx.z;
    const int y0 = n0 >> 6;

    const float* Ag = g_wt + (size_t)b*KTOT*COn + m0;             // A[k][m] = Ag[k*CO + m]
    const float* Xb = g_xpad + (size_t)b*CIn*HPn*HPn;

    // G2S mapping
    const int a_row = tid >> 5;            // k rows: a_row, a_row+8
    const int a_col = (tid & 31) * 4;      // m (float4)
    const int b_n = tid & 127;
    const int b_k0 = tid >> 7;             // k rows: b_k0 + 2*i
    const int b_r = b_n >> 6, b_x = b_n & 63;

    const int tg = lane & 3, gr = lane >> 2;

    float acc[4][4][4];
    #pragma unroll
    for (int i = 0; i < 4; i++)
        #pragma unroll
        for (int j = 0; j < 4; j++)
            #pragma unroll
            for (int q = 0; q < 4; q++) acc[i][j][q] = 0.f;

    float4 rA0, rA1;
    float rB[8];

    // prologue: tile 0 -> smem buf 0
    {
        const float* p = Ag + (size_t)a_row*COn + a_col;
        rA0 = *(const float4*)p;
        rA1 = *(const float4*)(p + 8*COn);
        #pragma unroll
        for (int i = 0; i < 8; i++) {
            const int k = b_k0 + 2*i;
            const int ci = k / 9, tap = k - ci*9;
            const int ky = tap / 3, kx = tap - ky*3;
            rB[i] = Xb[((size_t)ci*HPn + (y0 + b_r + ky))*HPn + (b_x + kx)];
        }
        float* sa = As[0] + a_row*LDSA + a_col;
        *(float4*)sa = rA0;
        *(float4*)(sa + 8*LDSA) = rA1;
        #pragma unroll
        for (int i = 0; i < 8; i++) Bs[0][(b_k0 + 2*i)*LDSA + b_n] = rB[i];
    }
    __syncthreads();

    int buf = 0;
    const int NKT = KTOT / KT;   // 288
    for (int t = 0; t < NKT; t++) {
        // prefetch next tile into registers
        if (t + 1 < NKT) {
            const int k0 = (t + 1) * KT;
            const float* p = Ag + (size_t)(k0 + a_row)*COn + a_col;
            rA0 = *(const float4*)p;
            rA1 = *(const float4*)(p + 8*COn);
            #pragma unroll
            for (int i = 0; i < 8; i++) {
                const int k = k0 + b_k0 + 2*i;
                const int ci = k / 9, tap = k - ci*9;
                const int ky = tap / 3, kx = tap - ky*3;
                rB[i] = Xb[((size_t)ci*HPn + (y0 + b_r + ky))*HPn + (b_x + kx)];
            }
        }
        // compute current tile
        const float* As_ = As[buf];
        const float* Bs_ = Bs[buf];
        #pragma unroll
        for (int kb = 0; kb < KT; kb += 8) {
            uint32_t af[4][4], bfr[4][2];
            #pragma unroll
            for (int mi = 0; mi < 4; mi++) {
                const int m = wm*64 + mi*16 + gr;
                const float* pa = As_ + (kb + tg)*LDSA + m;
                af[mi][0] = __float_as_uint(pa[0]);
                af[mi][1] = __float_as_uint(pa[8]);
                af[mi][2] = __float_as_uint(pa[4*LDSA]);
                af[mi][3] = __float_as_uint(pa[4*LDSA + 8]);
            }
            #pragma unroll
            for (int ni = 0; ni < 4; ni++) {
                const int n = wn*32 + ni*8 + gr;
                const float* pb = Bs_ + (kb + tg)*LDSA + n;
                bfr[ni][0] = __float_as_uint(pb[0]);
                bfr[ni][1] = __float_as_uint(pb[4*LDSA]);
            }
            #pragma unroll
            for (int mi = 0; mi < 4; mi++)
                #pragma unroll
                for (int ni = 0; ni < 4; ni++)
                    mma_tf32(acc[mi][ni], af[mi], bfr[ni]);
        }
        // stage next tile into other buffer
        if (t + 1 < NKT) {
            const int nb = buf ^ 1;
            float* sa = As[nb] + a_row*LDSA + a_col;
            *(float4*)sa = rA0;
            *(float4*)(sa + 8*LDSA) = rA1;
            #pragma unroll
            for (int i = 0; i < 8; i++) Bs[nb][(b_k0 + 2*i)*LDSA + b_n] = rB[i];
            __syncthreads();
            buf = nb;
        }
    }

    // fused epilogue: + noise_w*noise + bias, leaky_relu(0.2) * sqrt(2)
    const float nw = noise_w[0];
    const float SQ2 = 1.4142135623730951f;
    #pragma unroll
    for (int mi = 0; mi < 4; mi++) {
        #pragma unroll
        for (int h = 0; h < 2; h++) {
            const int co = m0 + wm*64 + mi*16 + gr + 8*h;
            const float bias = act_b[co];
            const float* np = noise + (size_t)(b*COn + co)*HWn;
            float* op = out + (size_t)(b*COn + co)*HWn;
            #pragma unroll
            for (int ni = 0; ni < 4; ni++) {
                const int n = n0 + wn*32 + ni*8 + tg*2;
                #pragma unroll
                for (int q = 0; q < 2; q++) {
                    float v = acc[mi][ni][2*h + q] + nw * np[n + q] + bias;
                    v = (v > 0.f ? v : 0.2f * v) * SQ2;
                    op[n + q] = v;
                }
            }
        }
    }
}

// ---------------- launch ----------------
extern "C" void kernel_launch(void* const* d_in, const int* in_sizes, int n_in,
                              void* d_out, int out_size) {
    (void)in_sizes; (void)n_in; (void)out_size;
    const float* x        = (const float*)d_in[0];  // [8,512,64,64]
    const float* style    = (const float*)d_in[1];  // [8,512]
    const float* noise    = (const float*)d_in[2];  // [8,512,64,64]
    const float* weight   = (const float*)d_in[3];  // [1,512,512,3,3]
    const float* mod_w    = (const float*)d_in[4];  // [512,512]
    const float* mod_b    = (const float*)d_in[5];  // [512]
    const float* noise_w  = (const float*)d_in[6];  // [1]
    const float* act_b    = (const float*)d_in[7];  // [512]
    float* out = (float*)d_out;

    k_style<<<Bn, 512>>>(style, mod_w, mod_b);
    k_demod<<<Bn*COn, 256>>>(weight);
    dim3 gw(KTOT/32, COn/32, Bn);
    k_wt<<<gw, dim3(32, 8)>>>(weight);
    k_pad<<<Bn*CIn, 256>>>(x);
    dim3 gc(HWn/BN, COn/BM, Bn);
    k_conv<<<gc, 256>>>(noise, noise_w, act_b, out);
}

// round 7
// speedup vs baseline: 2.4640x; 2.4640x over previous
#include <cuda_runtime.h>
#include <cuda_fp16.h>
#include <cstdint>

#define Bn   8
#define CIn  512
#define COn  512
#define KSn  3
#define WDn  512
#define Hn   64
#define HPn  66
#define KTOT (CIn*KSn*KSn)   // 4608
#define HWn  (Hn*Hn)         // 4096

// conv tiling
#define TM   128             // co per CTA
#define TN   128             // hw per CTA (2 image rows)
#define KT   32              // K per stage
#define NK   (KTOT/KT)       // 144
#define AS_B (TM*80)         // A stage: 128 rows x (64B data + 16B pad) = 10240
#define BS_B (KT*256)        // B stage: 32 k-rows x 128 halfs = 8192

// ---------------- scratch (device globals; no allocations) ----------------
static __device__ float  g_s[Bn*CIn];
static __device__ float  g_demod[Bn*COn];
static __device__ __align__(16) __half g_wt[(size_t)Bn*COn*KTOT];       // [b][co][k] fp16
static __device__ __align__(16) __half g_xpad[(size_t)Bn*CIn*HPn*HPn];  // padded input fp16

// ---------------- PTX helpers ----------------
__device__ __forceinline__ uint32_t smem_u32(const void* p) {
    uint32_t a;
    asm("{ .reg .u64 t; cvta.to.shared.u64 t, %1; cvt.u32.u64 %0, t; }" : "=r"(a) : "l"(p));
    return a;
}
__device__ __forceinline__ void ldsm_x4(uint32_t r[4], uint32_t a) {
    asm volatile("ldmatrix.sync.aligned.m8n8.x4.shared.b16 {%0,%1,%2,%3}, [%4];"
        : "=r"(r[0]), "=r"(r[1]), "=r"(r[2]), "=r"(r[3]) : "r"(a));
}
__device__ __forceinline__ void ldsm_x4t(uint32_t r[4], uint32_t a) {
    asm volatile("ldmatrix.sync.aligned.m8n8.x4.trans.shared.b16 {%0,%1,%2,%3}, [%4];"
        : "=r"(r[0]), "=r"(r[1]), "=r"(r[2]), "=r"(r[3]) : "r"(a));
}
__device__ __forceinline__ void mma16816(float c[4], const uint32_t a[4],
                                         uint32_t b0, uint32_t b1) {
    asm volatile(
        "mma.sync.aligned.m16n8k16.row.col.f32.f16.f16.f32 "
        "{%0,%1,%2,%3},{%4,%5,%6,%7},{%8,%9},{%0,%1,%2,%3};"
        : "+f"(c[0]), "+f"(c[1]), "+f"(c[2]), "+f"(c[3])
        : "r"(a[0]), "r"(a[1]), "r"(a[2]), "r"(a[3]), "r"(b0), "r"(b1));
}

// ---------------- 1) style modulation ----------------
__global__ void k_style(const float* __restrict__ style,
                        const float* __restrict__ mw,
                        const float* __restrict__ mb) {
    const int b = blockIdx.x;
    const int ci = threadIdx.x;            // blockDim = 512
    __shared__ float st[WDn];
    st[ci] = style[b*WDn + ci];
    __syncthreads();
    const float eq = 0.044194173824159216f;  // 1/sqrt(512)
    const float* row = mw + (size_t)ci*WDn;
    float acc = 0.f;
    #pragma unroll 8
    for (int w = 0; w < WDn; w++) acc += st[w] * row[w];
    g_s[b*CIn + ci] = acc * eq + mb[ci];
}

// ---------------- 2) demod ----------------
__global__ void k_demod(const float* __restrict__ weight) {
    const int bc = blockIdx.x;             // b*512 + co
    const int b = bc >> 9, co = bc & 511;
    const float* w = weight + (size_t)co*KTOT;
    const float* s = g_s + b*CIn;
    float acc = 0.f;
    for (int i = threadIdx.x; i < KTOT; i += 256) {
        float v = w[i] * s[i / 9];
        acc += v * v;
    }
    #pragma unroll
    for (int o = 16; o; o >>= 1) acc += __shfl_xor_sync(0xffffffffu, acc, o);
    __shared__ float red[8];
    if ((threadIdx.x & 31) == 0) red[threadIdx.x >> 5] = acc;
    __syncthreads();
    if (threadIdx.x == 0) {
        float t = 0.f;
        #pragma unroll
        for (int i = 0; i < 8; i++) t += red[i];
        const float cs2 = 1.0f / (float)KTOT;
        g_demod[bc] = rsqrtf(cs2 * t + 1e-8f);
    }
}

// ---------------- 3) modulated weights -> fp16, K-major [b][co][k] ----------------
__global__ void k_wt(const float* __restrict__ weight) {
    const int bc = blockIdx.x;             // b*512 + co
    const int b = bc >> 9, co = bc & 511;
    const float CS = 0.014731391274719742f;  // 1/sqrt(4608)
    const float dm = g_demod[bc] * CS;
    const float* w = weight + (size_t)co*KTOT;
    const float* s = g_s + b*CIn;
    __half* o = g_wt + (size_t)bc*KTOT;
    for (int i = threadIdx.x; i < KTOT; i += 256)
        o[i] = __float2half_rn(w[i] * s[i / 9] * dm);
}

// ---------------- 4) zero-padded fp16 input ----------------
__global__ void k_pad(const float* __restrict__ x) {
    const int plane = blockIdx.x;          // b*CI + ci
    const float* src = x + (size_t)plane * HWn;
    __half* dst = g_xpad + (size_t)plane * HPn * HPn;
    for (int i = threadIdx.x; i < HPn*HPn; i += blockDim.x) {
        const int y = i / HPn, xx = i % HPn;
        float v = 0.f;
        if (y >= 1 && y <= Hn && xx >= 1 && xx <= Hn)
            v = src[(y-1)*Hn + (xx-1)];
        dst[i] = __float2half_rn(v);
    }
}

// ---------------- 5) fp16 mma implicit-GEMM conv + fused epilogue ----------------
__global__ void __launch_bounds__(256) k_conv(const float* __restrict__ noise,
                                              const float* __restrict__ noise_w,
                                              const float* __restrict__ act_b,
                                              float* __restrict__ out) {
    __shared__ __align__(16) unsigned char sm[2*(AS_B + BS_B)];
    const uint32_t sbase = smem_u32(sm);

    const int tid = threadIdx.x, lane = tid & 31, warp = tid >> 5;
    const int wm = warp & 1, wn = warp >> 1;        // 2 x 4 warp grid
    const int n0 = blockIdx.x * TN;                 // hw tile (2 image rows)
    const int m0 = blockIdx.y * TM;                 // co tile
    const int b  = blockIdx.z;
    const int y0 = n0 >> 6;

    const __half* Ag = g_wt + (size_t)(b*COn + m0) * KTOT;    // [co][k]
    const __half* Xb = g_xpad + (size_t)b * CIn * HPn * HPn;

    // A g2s map: idx=(tid, tid+256) -> (m = idx>>2, chunk c = idx&3)
    const int am = tid >> 2, ac = tid & 3;
    // B gather map: thread -> (k-row bk, n segment of 16)
    const int bk = tid >> 3;
    const int seg = tid & 7;
    const int br = seg >> 2, bx0 = (seg & 3) * 16;
    const int nseg0 = seg * 16;

    // ldmatrix per-lane offsets
    const uint32_t a_lane = (uint32_t)((wm*64 + (lane & 15)) * 80 + (lane >> 4) * 16);
    const int krow0 = ((lane >> 3) & 1) * 8 + (lane & 7);
    const int bc0 = wn * 4 + (lane >> 4);
    const uint32_t b_off0 = (uint32_t)(krow0 * 256 + ((bc0 + 0) ^ (krow0 & 7)) * 16);
    const uint32_t b_off1 = (uint32_t)(krow0 * 256 + ((bc0 + 2) ^ (krow0 & 7)) * 16);

    float acc[4][4][4];
    #pragma unroll
    for (int i = 0; i < 4; i++)
        #pragma unroll
        for (int j = 0; j < 4; j++)
            #pragma unroll
            for (int q = 0; q < 4; q++) acc[i][j][q] = 0.f;

    uint4 ar0, ar1;
    uint32_t bw[8];

    // ---- gather stage t into registers ----
    auto gather = [&](int t) {
        const int k0 = t * KT;
        const __half* ap = Ag + (size_t)am * KTOT + k0 + ac * 8;
        ar0 = *(const uint4*)ap;
        ar1 = *(const uint4*)(ap + (size_t)64 * KTOT);
        const int kg = k0 + bk;
        const int ci = kg / 9, tap = kg - 9 * ci;
        const int ky = tap / 3, kx = tap - 3 * ky;
        const unsigned short* s16 = (const unsigned short*)
            (Xb + (size_t)ci * (HPn*HPn) + (size_t)(y0 + br + ky) * HPn + (bx0 + kx));
        #pragma unroll
        for (int j = 0; j < 8; j++) {
            unsigned lo = s16[2*j], hi = s16[2*j + 1];
            bw[j] = lo | (hi << 16);
        }
    };
    // ---- store registers to smem stage buf ----
    auto stage = [&](int buf) {
        unsigned char* A = sm + buf * (AS_B + BS_B);
        *(uint4*)(A + am*80 + ac*16) = ar0;
        *(uint4*)(A + (am + 64)*80 + ac*16) = ar1;
        unsigned char* Bp = A + AS_B + bk * 256;
        #pragma unroll
        for (int j = 0; j < 8; j++) {
            const int n = nseg0 + 2*j;
            const int ch = (n >> 3) ^ (bk & 7);
            *(uint32_t*)(Bp + ch*16 + (n & 7)*2) = bw[j];
        }
    };
    // ---- mma over stage buf ----
    auto compute = [&](int buf) {
        const uint32_t aB = sbase + buf * (AS_B + BS_B);
        const uint32_t bB = aB + AS_B;
        #pragma unroll
        for (int kb = 0; kb < KT; kb += 16) {
            uint32_t af[4][4], bf[2][4];
            #pragma unroll
            for (int mi = 0; mi < 4; mi++)
                ldsm_x4(af[mi], aB + a_lane + mi*(16*80) + (kb >> 3)*16);
            ldsm_x4t(bf[0], bB + b_off0 + kb*256);
            ldsm_x4t(bf[1], bB + b_off1 + kb*256);
            #pragma unroll
            for (int mi = 0; mi < 4; mi++) {
                #pragma unroll
                for (int it = 0; it < 2; it++) {
                    mma16816(acc[mi][it*2 + 0], af[mi], bf[it][0], bf[it][1]);
                    mma16816(acc[mi][it*2 + 1], af[mi], bf[it][2], bf[it][3]);
                }
            }
        }
    };

    // prologue
    gather(0);
    stage(0);
    __syncthreads();

    for (int t = 0; t < NK; t++) {
        if (t + 1 < NK) gather(t + 1);
        compute(t & 1);
        if (t + 1 < NK) {
            stage((t + 1) & 1);
            __syncthreads();
        }
    }

    // fused epilogue: + noise_w*noise + bias, leaky_relu(0.2) * sqrt(2)
    const int gr = lane >> 2, tg = lane & 3;
    const float nw = noise_w[0];
    const float SQ2 = 1.4142135623730951f;
    #pragma unroll
    for (int mi = 0; mi < 4; mi++) {
        #pragma unroll
        for (int h = 0; h < 2; h++) {
            const int co = m0 + wm*64 + mi*16 + gr + 8*h;
            const float bias = act_b[co];
            const float* np = noise + (size_t)(b*COn + co) * HWn;
            float* op = out + (size_t)(b*COn + co) * HWn;
            #pragma unroll
            for (int ni = 0; ni < 4; ni++) {
                const int n = n0 + wn*32 + ni*8 + tg*2;
                float2 nv = *(const float2*)(np + n);
                float v0 = acc[mi][ni][2*h + 0] + nw * nv.x + bias;
                float v1 = acc[mi][ni][2*h + 1] + nw * nv.y + bias;
                float2 ov;
                ov.x = (v0 > 0.f ? v0 : 0.2f*v0) * SQ2;
                ov.y = (v1 > 0.f ? v1 : 0.2f*v1) * SQ2;
                *(float2*)(op + n) = ov;
            }
        }
    }
}

// ---------------- launch ----------------
extern "C" void kernel_launch(void* const* d_in, const int* in_sizes, int n_in,
                              void* d_out, int out_size) {
    (void)in_sizes; (void)n_in; (void)out_size;
    const float* x        = (const float*)d_in[0];  // [8,512,64,64]
    const float* style    = (const float*)d_in[1];  // [8,512]
    const float* noise    = (const float*)d_in[2];  // [8,512,64,64]
    const float* weight   = (const float*)d_in[3];  // [1,512,512,3,3]
    const float* mod_w    = (const float*)d_in[4];  // [512,512]
    const float* mod_b    = (const float*)d_in[5];  // [512]
    const float* noise_w  = (const float*)d_in[6];  // [1]
    const float* act_b    = (const float*)d_in[7];  // [512]
    float* out = (float*)d_out;

    k_style<<<Bn, 512>>>(style, mod_w, mod_b);
    k_demod<<<Bn*COn, 256>>>(weight);
    k_wt<<<Bn*COn, 256>>>(weight);
    k_pad<<<Bn*CIn, 256>>>(x);
    dim3 gc(HWn/TN, COn/TM, Bn);
    k_conv<<<gc, 256>>>(noise, noise_w, act_b, out);
}

// round 8
// speedup vs baseline: 3.2709x; 1.3275x over previous
#include <cuda_runtime.h>
#include <cuda_fp16.h>
#include <cstdint>

#define Bn   8
#define CIn  512
#define COn  512
#define WDn  512
#define Hn   64
#define HPn  66
#define RS   72                  // padded row stride (halves), 144B = 16B aligned
#define PS   (HPn*RS)            // plane stride in halves (4752)
#define KTOT 4608
#define KP   1536                // K per ky-pass (ci*3)

// conv tiling
#define TM   128                 // co per CTA
#define TN   128                 // hw per CTA (2 image rows)
#define KT   48                  // K per stage = 16 ci x 3 kx
#define NSTAGE 96                // 3 passes x 32 stages
#define A_STRIDE 112             // 96B data + 16B pad (112/8 odd -> conflict-free ldmatrix)
#define AS_B (TM*A_STRIDE)       // 14336
#define BS_B (KT*256)            // 12288
#define STG  (AS_B + BS_B)       // 26624
#define SMEM_TOTAL (2*STG)       // 53248 (dynamic)

// ---------------- scratch (device globals; no allocations) ----------------
static __device__ float  g_s[Bn*CIn];
static __device__ float  g_demod[Bn*COn];
// weights reordered: [b][ky][co][ci*3+kx], fp16
static __device__ __align__(16) __half g_wt[(size_t)Bn*3*COn*KP];
// padded input, row stride 72: [b*CI + ci][row][72]
static __device__ __align__(16) __half g_xpad[(size_t)Bn*CIn*PS];

// ---------------- PTX helpers ----------------
__device__ __forceinline__ uint32_t smem_u32(const void* p) {
    uint32_t a;
    asm("{ .reg .u64 t; cvta.to.shared.u64 t, %1; cvt.u32.u64 %0, t; }" : "=r"(a) : "l"(p));
    return a;
}
__device__ __forceinline__ void ldsm_x4(uint32_t r[4], uint32_t a) {
    asm volatile("ldmatrix.sync.aligned.m8n8.x4.shared.b16 {%0,%1,%2,%3}, [%4];"
        : "=r"(r[0]), "=r"(r[1]), "=r"(r[2]), "=r"(r[3]) : "r"(a));
}
__device__ __forceinline__ void ldsm_x4t(uint32_t r[4], uint32_t a) {
    asm volatile("ldmatrix.sync.aligned.m8n8.x4.trans.shared.b16 {%0,%1,%2,%3}, [%4];"
        : "=r"(r[0]), "=r"(r[1]), "=r"(r[2]), "=r"(r[3]) : "r"(a));
}
__device__ __forceinline__ void mma16816(float c[4], const uint32_t a[4],
                                         uint32_t b0, uint32_t b1) {
    asm volatile(
        "mma.sync.aligned.m16n8k16.row.col.f32.f16.f16.f32 "
        "{%0,%1,%2,%3},{%4,%5,%6,%7},{%8,%9},{%0,%1,%2,%3};"
        : "+f"(c[0]), "+f"(c[1]), "+f"(c[2]), "+f"(c[3])
        : "r"(a[0]), "r"(a[1]), "r"(a[2]), "r"(a[3]), "r"(b0), "r"(b1));
}

// ---------------- 1) style modulation ----------------
__global__ void k_style(const float* __restrict__ style,
                        const float* __restrict__ mw,
                        const float* __restrict__ mb) {
    const int b = blockIdx.x;
    const int ci = threadIdx.x;            // blockDim = 512
    __shared__ float st[WDn];
    st[ci] = style[b*WDn + ci];
    __syncthreads();
    const float eq = 0.044194173824159216f;  // 1/sqrt(512)
    const float* row = mw + (size_t)ci*WDn;
    float acc = 0.f;
    #pragma unroll 8
    for (int w = 0; w < WDn; w++) acc += st[w] * row[w];
    g_s[b*CIn + ci] = acc * eq + mb[ci];
}

// ---------------- 2) demod ----------------
__global__ void k_demod(const float* __restrict__ weight) {
    const int bc = blockIdx.x;             // b*512 + co
    const int b = bc >> 9, co = bc & 511;
    const float* w = weight + (size_t)co*KTOT;
    const float* s = g_s + b*CIn;
    float acc = 0.f;
    for (int i = threadIdx.x; i < KTOT; i += 256) {
        float v = w[i] * s[i / 9];
        acc += v * v;
    }
    #pragma unroll
    for (int o = 16; o; o >>= 1) acc += __shfl_xor_sync(0xffffffffu, acc, o);
    __shared__ float red[8];
    if ((threadIdx.x & 31) == 0) red[threadIdx.x >> 5] = acc;
    __syncthreads();
    if (threadIdx.x == 0) {
        float t = 0.f;
        #pragma unroll
        for (int i = 0; i < 8; i++) t += red[i];
        const float cs2 = 1.0f / (float)KTOT;
        g_demod[bc] = rsqrtf(cs2 * t + 1e-8f);
    }
}

// ---------------- 3) modulated weights -> fp16, [b][ky][co][ci*3+kx] ----------------
__global__ void k_wt(const float* __restrict__ weight) {
    const int bc = blockIdx.x;             // b*512 + co
    const int b = bc >> 9, co = bc & 511;
    const float CS = 0.014731391274719742f;  // 1/sqrt(4608)
    const float dm = g_demod[bc] * CS;
    const float* w = weight + (size_t)co*KTOT;
    const float* s = g_s + b*CIn;
    for (int j = threadIdx.x; j < KTOT; j += 256) {
        const int ky = j / KP;
        const int jj = j - ky * KP;        // ci*3 + kx
        const int ci = jj / 3, kx = jj - 3*ci;
        const float v = w[ci*9 + ky*3 + kx] * s[ci] * dm;
        g_wt[((size_t)(b*3 + ky)*COn + co)*KP + jj] = __float2half_rn(v);
    }
}

// ---------------- 4) zero-padded fp16 input, row stride 72 ----------------
__global__ void k_pad(const float* __restrict__ x) {
    const int plane = blockIdx.x;          // b*CI + ci
    const float* src = x + (size_t)plane * (Hn*Hn);
    __half* dst = g_xpad + (size_t)plane * PS;
    for (int i = threadIdx.x; i < HPn*18; i += blockDim.x) {
        const int y = i / 18, x0 = (i - y*18) * 4;
        __half h[4];
        #pragma unroll
        for (int d = 0; d < 4; d++) {
            const int xx = x0 + d;
            float v = 0.f;
            if (y >= 1 && y <= Hn && xx >= 1 && xx <= Hn)
                v = src[(y-1)*Hn + (xx-1)];
            h[d] = __float2half_rn(v);
        }
        *(uint2*)(dst + y*RS + x0) = *(uint2*)h;
    }
}

// ---------------- 5) fp16 mma implicit-GEMM conv, 3 ky passes ----------------
__global__ void __launch_bounds__(256) k_conv(const float* __restrict__ noise,
                                              const float* __restrict__ noise_w,
                                              const float* __restrict__ act_b,
                                              float* __restrict__ out) {
    extern __shared__ __align__(16) unsigned char sm[];
    const uint32_t sbase = smem_u32(sm);

    const int tid = threadIdx.x, lane = tid & 31, warp = tid >> 5;
    const int wm = warp & 1, wn = warp >> 1;        // 2 x 4 warp grid
    const int n0 = blockIdx.x * TN;                 // hw tile (2 image rows)
    const int m0 = blockIdx.y * TM;                 // co tile
    const int b  = blockIdx.z;
    const int y0 = n0 >> 6;                         // first image row

    const int am = tid >> 1;                        // A: co row 0..127
    const int ah = (tid & 1) * 24;                  // A: half offset in row
    const int ci_l = tid >> 4;                      // B: local ci 0..15
    const int br = (tid >> 3) & 1;                  // B: image row in tile
    const int xs = tid & 7;                         // B: x segment (8 halves)
    const int n8 = br * 8 + xs;                     // n-chunk index 0..15

    const uint32_t a_lane = (uint32_t)((wm*64 + (lane & 15)) * A_STRIDE + (lane >> 4) * 16);
    const int krow0 = lane & 15;
    const int bc0 = wn * 4 + (lane >> 4);
    const uint32_t b_off0 = (uint32_t)(krow0 * 256 + ((bc0 + 0) ^ (krow0 & 7)) * 16);
    const uint32_t b_off1 = (uint32_t)(krow0 * 256 + ((bc0 + 2) ^ (krow0 & 7)) * 16);

    float acc[4][4][4];
    #pragma unroll
    for (int i = 0; i < 4; i++)
        #pragma unroll
        for (int j = 0; j < 4; j++)
            #pragma unroll
            for (int q = 0; q < 4; q++) acc[i][j][q] = 0.f;

    uint4 ar[3];
    uint4 wv;
    uint32_t wx;

    const __half* Xplane = g_xpad + (size_t)b * CIn * PS;

    auto gather = [&](int t) {
        const int ky = t >> 5;
        const int k0 = (t & 31) * KT;
        const __half* ap = g_wt
            + ((size_t)(b*3 + ky)*COn + m0 + am) * KP + k0 + ah;
        ar[0] = *(const uint4*)(ap);
        ar[1] = *(const uint4*)(ap + 8);
        ar[2] = *(const uint4*)(ap + 16);
        const int ci = (k0 / 3) + ci_l;
        const __half* bp = Xplane + (size_t)ci * PS + (y0 + br + ky) * RS + xs * 8;
        wv = *(const uint4*)bp;
        wx = *(const uint32_t*)(bp + 8);
    };
    auto stage = [&](int buf) {
        unsigned char* A = sm + buf * STG;
        *(uint4*)(A + am*A_STRIDE + ah*2)      = ar[0];
        *(uint4*)(A + am*A_STRIDE + ah*2 + 16) = ar[1];
        *(uint4*)(A + am*A_STRIDE + ah*2 + 32) = ar[2];
        unsigned char* Bp = A + AS_B;
        const int kb = ci_l * 3;
        {
            const int k = kb;
            *(uint4*)(Bp + k*256 + ((n8 ^ (k & 7)) * 16)) = wv;
        }
        {
            const int k = kb + 1;
            uint4 v;
            v.x = __funnelshift_r(wv.x, wv.y, 16);
            v.y = __funnelshift_r(wv.y, wv.z, 16);
            v.z = __funnelshift_r(wv.z, wv.w, 16);
            v.w = __funnelshift_r(wv.w, wx,   16);
            *(uint4*)(Bp + k*256 + ((n8 ^ (k & 7)) * 16)) = v;
        }
        {
            const int k = kb + 2;
            uint4 v; v.x = wv.y; v.y = wv.z; v.z = wv.w; v.w = wx;
            *(uint4*)(Bp + k*256 + ((n8 ^ (k & 7)) * 16)) = v;
        }
    };
    auto compute = [&](int buf) {
        const uint32_t aB = sbase + buf * STG;
        const uint32_t bB = aB + AS_B;
        #pragma unroll
        for (int kb = 0; kb < KT; kb += 16) {
            uint32_t af[4][4], bf[2][4];
            #pragma unroll
            for (int mi = 0; mi < 4; mi++)
                ldsm_x4(af[mi], aB + a_lane + mi*(16*A_STRIDE) + kb*2);
            ldsm_x4t(bf[0], bB + b_off0 + kb*256);
            ldsm_x4t(bf[1], bB + b_off1 + kb*256);
            #pragma unroll
            for (int mi = 0; mi < 4; mi++) {
                #pragma unroll
                for (int it = 0; it < 2; it++) {
                    mma16816(acc[mi][it*2 + 0], af[mi], bf[it][0], bf[it][1]);
                    mma16816(acc[mi][it*2 + 1], af[mi], bf[it][2], bf[it][3]);
                }
            }
        }
    };

    gather(0);
    stage(0);
    __syncthreads();

    for (int t = 0; t < NSTAGE; t++) {
        if (t + 1 < NSTAGE) gather(t + 1);
        compute(t & 1);
        if (t + 1 < NSTAGE) {
            stage((t + 1) & 1);
            __syncthreads();
        }
    }

    // fused epilogue
    const int gr = lane >> 2, tg = lane & 3;
    const float nw = noise_w[0];
    const float SQ2 = 1.4142135623730951f;
    #pragma unroll
    for (int mi = 0; mi < 4; mi++) {
        #pragma unroll
        for (int h = 0; h < 2; h++) {
            const int co = m0 + wm*64 + mi*16 + gr + 8*h;
            const float bias = act_b[co];
            const float* np = noise + (size_t)(b*COn + co) * (Hn*Hn);
            float* op = out + (size_t)(b*COn + co) * (Hn*Hn);
            #pragma unroll
            for (int ni = 0; ni < 4; ni++) {
                const int n = n0 + wn*32 + ni*8 + tg*2;
                float2 nv = *(const float2*)(np + n);
                float v0 = acc[mi][ni][2*h + 0] + nw * nv.x + bias;
                float v1 = acc[mi][ni][2*h + 1] + nw * nv.y + bias;
                float2 ov;
                ov.x = (v0 > 0.f ? v0 : 0.2f*v0) * SQ2;
                ov.y = (v1 > 0.f ? v1 : 0.2f*v1) * SQ2;
                *(float2*)(op + n) = ov;
            }
        }
    }
}

// ---------------- launch ----------------
extern "C" void kernel_launch(void* const* d_in, const int* in_sizes, int n_in,
                              void* d_out, int out_size) {
    (void)in_sizes; (void)n_in; (void)out_size;
    const float* x        = (const float*)d_in[0];  // [8,512,64,64]
    const float* style    = (const float*)d_in[1];  // [8,512]
    const float* noise    = (const float*)d_in[2];  // [8,512,64,64]
    const float* weight   = (const float*)d_in[3];  // [1,512,512,3,3]
    const float* mod_w    = (const float*)d_in[4];  // [512,512]
    const float* mod_b    = (const float*)d_in[5];  // [512]
    const float* noise_w  = (const float*)d_in[6];  // [1]
    const float* act_b    = (const float*)d_in[7];  // [512]
    float* out = (float*)d_out;

    cudaFuncSetAttribute(k_conv, cudaFuncAttributeMaxDynamicSharedMemorySize, SMEM_TOTAL);

    k_style<<<Bn, 512>>>(style, mod_w, mod_b);
    k_demod<<<Bn*COn, 256>>>(weight);
    k_wt<<<Bn*COn, 256>>>(weight);
    k_pad<<<Bn*CIn, 256>>>(x);
    dim3 gc((Hn*Hn)/TN, COn/TM, Bn);
    k_conv<<<gc, 256, SMEM_TOTAL>>>(noise, noise_w, act_b, out);
}

// round 11
// speedup vs baseline: 3.4550x; 1.0563x over previous
#include <cuda_runtime.h>
#include <cuda_fp16.h>
#include <cstdint>

#define Bn   8
#define CIn  512
#define COn  512
#define WDn  512
#define Hn   64
#define HPn  66
#define RS   72                  // padded row stride (halves), 144B = 16B aligned
#define PS   (HPn*RS)            // plane stride in halves (4752)
#define KTOT 4608
#define KP   1536                // K per ky-pass (ci*3)

// conv tiling
#define TM   128                 // co per CTA
#define TN   256                 // hw per CTA (4 image rows)
#define KT   48                  // K per stage = 16 ci x 3 kx
#define NSTAGE 96                // 3 passes x 32 stages
#define A_STRIDE 112             // 96B data + 16B pad (conflict-free ldmatrix)
#define AS_B (TM*A_STRIDE)       // 14336
#define BS_B (KT*512)            // 24576 (256 halves per k-row)
#define STG  (AS_B + BS_B)       // 38912
#define SMEM_TOTAL (2*STG)       // 77824 (dynamic)
#define NT   512                 // threads per CTA

// ---------------- scratch (device globals; no allocations) ----------------
static __device__ float  g_s[Bn*CIn];
static __device__ float  g_demod[Bn*COn];
// weights reordered: [b][ky][co][ci*3+kx], fp16
static __device__ __align__(16) __half g_wt[(size_t)Bn*3*COn*KP];
// padded input, row stride 72: [b*CI + ci][row][72]
static __device__ __align__(16) __half g_xpad[(size_t)Bn*CIn*PS];

// ---------------- PTX helpers ----------------
__device__ __forceinline__ uint32_t smem_u32(const void* p) {
    uint32_t a;
    asm("{ .reg .u64 t; cvta.to.shared.u64 t, %1; cvt.u32.u64 %0, t; }" : "=r"(a) : "l"(p));
    return a;
}
__device__ __forceinline__ void cpasync16(uint32_t dst, const void* src) {
    asm volatile("cp.async.cg.shared.global [%0], [%1], 16;" :: "r"(dst), "l"(src));
}
__device__ __forceinline__ void cpasync_commit() {
    asm volatile("cp.async.commit_group;");
}
__device__ __forceinline__ void cpasync_wait0() {
    asm volatile("cp.async.wait_group 0;");
}
__device__ __forceinline__ void ldsm_x4(uint32_t r[4], uint32_t a) {
    asm volatile("ldmatrix.sync.aligned.m8n8.x4.shared.b16 {%0,%1,%2,%3}, [%4];"
        : "=r"(r[0]), "=r"(r[1]), "=r"(r[2]), "=r"(r[3]) : "r"(a));
}
__device__ __forceinline__ void ldsm_x4t(uint32_t r[4], uint32_t a) {
    asm volatile("ldmatrix.sync.aligned.m8n8.x4.trans.shared.b16 {%0,%1,%2,%3}, [%4];"
        : "=r"(r[0]), "=r"(r[1]), "=r"(r[2]), "=r"(r[3]) : "r"(a));
}
__device__ __forceinline__ void mma16816(float c[4], const uint32_t a[4],
                                         uint32_t b0, uint32_t b1) {
    asm volatile(
        "mma.sync.aligned.m16n8k16.row.col.f32.f16.f16.f32 "
        "{%0,%1,%2,%3},{%4,%5,%6,%7},{%8,%9},{%0,%1,%2,%3};"
        : "+f"(c[0]), "+f"(c[1]), "+f"(c[2]), "+f"(c[3])
        : "r"(a[0]), "r"(a[1]), "r"(a[2]), "r"(a[3]), "r"(b0), "r"(b1));
}

// ---------------- 1) style modulation ----------------
__global__ void k_style(const float* __restrict__ style,
                        const float* __restrict__ mw,
                        const float* __restrict__ mb) {
    const int b = blockIdx.x;
    const int ci = threadIdx.x;            // blockDim = 512
    __shared__ float st[WDn];
    st[ci] = style[b*WDn + ci];
    __syncthreads();
    const float eq = 0.044194173824159216f;  // 1/sqrt(512)
    const float* row = mw + (size_t)ci*WDn;
    float acc = 0.f;
    #pragma unroll 8
    for (int w = 0; w < WDn; w++) acc += st[w] * row[w];
    g_s[b*CIn + ci] = acc * eq + mb[ci];
}

// ---------------- 2) demod ----------------
__global__ void k_demod(const float* __restrict__ weight) {
    const int bc = blockIdx.x;             // b*512 + co
    const int b = bc >> 9, co = bc & 511;
    const float* w = weight + (size_t)co*KTOT;
    const float* s = g_s + b*CIn;
    float acc = 0.f;
    for (int i = threadIdx.x; i < KTOT; i += 256) {
        float v = w[i] * s[i / 9];
        acc += v * v;
    }
    #pragma unroll
    for (int o = 16; o; o >>= 1) acc += __shfl_xor_sync(0xffffffffu, acc, o);
    __shared__ float red[8];
    if ((threadIdx.x & 31) == 0) red[threadIdx.x >> 5] = acc;
    __syncthreads();
    if (threadIdx.x == 0) {
        float t = 0.f;
        #pragma unroll
        for (int i = 0; i < 8; i++) t += red[i];
        const float cs2 = 1.0f / (float)KTOT;
        g_demod[bc] = rsqrtf(cs2 * t + 1e-8f);
    }
}

// ---------------- 3) modulated weights -> fp16, [b][ky][co][ci*3+kx] ----------------
__global__ void k_wt(const float* __restrict__ weight) {
    const int bc = blockIdx.x;             // b*512 + co
    const int b = bc >> 9, co = bc & 511;
    const float CS = 0.014731391274719742f;  // 1/sqrt(4608)
    const float dm = g_demod[bc] * CS;
    const float* w = weight + (size_t)co*KTOT;
    const float* s = g_s + b*CIn;
    for (int j = threadIdx.x; j < KTOT; j += 256) {
        const int ky = j / KP;
        const int jj = j - ky * KP;        // ci*3 + kx
        const int ci = jj / 3, kx = jj - 3*ci;
        const float v = w[ci*9 + ky*3 + kx] * s[ci] * dm;
        g_wt[((size_t)(b*3 + ky)*COn + co)*KP + jj] = __float2half_rn(v);
    }
}

// ---------------- 4) zero-padded fp16 input, row stride 72 ----------------
__global__ void k_pad(const float* __restrict__ x) {
    const int plane = blockIdx.x;          // b*CI + ci
    const float* src = x + (size_t)plane * (Hn*Hn);
    __half* dst = g_xpad + (size_t)plane * PS;
    for (int i = threadIdx.x; i < HPn*18; i += blockDim.x) {
        const int y = i / 18, x0 = (i - y*18) * 4;
        __half h[4];
        #pragma unroll
        for (int d = 0; d < 4; d++) {
            const int xx = x0 + d;
            float v = 0.f;
            if (y >= 1 && y <= Hn && xx >= 1 && xx <= Hn)
                v = src[(y-1)*Hn + (xx-1)];
            h[d] = __float2half_rn(v);
        }
        *(uint2*)(dst + y*RS + x0) = *(uint2*)h;
    }
}

// ---------------- 5) fp16 mma implicit-GEMM conv, 3 ky passes ----------------
__global__ void __launch_bounds__(NT, 1) k_conv(const float* __restrict__ noise,
                                                const float* __restrict__ noise_w,
                                                const float* __restrict__ act_b,
                                                float* __restrict__ out) {
    extern __shared__ __align__(16) unsigned char sm[];
    const uint32_t sbase = smem_u32(sm);

    const int tid = threadIdx.x, lane = tid & 31, warp = tid >> 5;
    const int wm = warp & 1, wn = warp >> 1;        // 2 x 8 warp grid
    const int n0 = blockIdx.x * TN;                 // hw tile (4 image rows)
    const int m0 = blockIdx.y * TM;                 // co tile
    const int b  = blockIdx.z;
    const int y0 = n0 >> 6;                         // first image row

    // A cp.async map: 768 chunks of 16B (128 rows x 6 chunks)
    const int a_r0 = tid / 6,        a_o0 = (tid - 6*a_r0) * 16;
    const int c1   = tid + NT;
    const int a_r1 = c1 / 6,         a_o1 = (c1 - 6*a_r1) * 16;
    const bool has1 = (tid < 768 - NT);
    // B g2s map: ci_l = warp (16), r = (tid>>3)&3, xs = tid&7
    const int ci_l = tid >> 5;
    const int br = (tid >> 3) & 3;
    const int xs = tid & 7;
    const int n8 = br * 8 + xs;                     // n-chunk 0..31

    // ldmatrix per-lane offsets
    const uint32_t a_lane = (uint32_t)((wm*64 + (lane & 15)) * A_STRIDE + (lane >> 4) * 16);
    const int krow0 = lane & 15;
    const int bc0 = wn * 4 + (lane >> 4);
    const int sw0 = ((bc0 + 0) & 24) | (((bc0 + 0) ^ (krow0 & 7)) & 7);
    const int sw1 = ((bc0 + 2) & 24) | (((bc0 + 2) ^ (krow0 & 7)) & 7);
    const uint32_t b_off0 = (uint32_t)(krow0 * 512 + sw0 * 16);
    const uint32_t b_off1 = (uint32_t)(krow0 * 512 + sw1 * 16);

    float acc[4][4][4];
    #pragma unroll
    for (int i = 0; i < 4; i++)
        #pragma unroll
        for (int j = 0; j < 4; j++)
            #pragma unroll
            for (int q = 0; q < 4; q++) acc[i][j][q] = 0.f;

    uint4 wv;
    uint32_t wx;

    const __half* Xplane = g_xpad + (size_t)b * CIn * PS;

    // ---- A tile: issue cp.async for stage t into buf ----
    auto issueA = [&](int t, int buf) {
        const int ky = t >> 5;
        const int k0 = (t & 31) * KT;
        const char* src = (const char*)(g_wt + ((size_t)(b*3 + ky)*COn + m0) * KP + k0);
        const uint32_t dst = sbase + buf * STG;
        cpasync16(dst + a_r0*A_STRIDE + a_o0, src + (size_t)a_r0*(KP*2) + a_o0);
        if (has1)
            cpasync16(dst + a_r1*A_STRIDE + a_o1, src + (size_t)a_r1*(KP*2) + a_o1);
        cpasync_commit();
    };
    // ---- B tile: gather raw row segment into registers ----
    auto gatherB = [&](int t) {
        const int ky = t >> 5;
        const int k0 = (t & 31) * KT;
        const int ci = (k0 / 3) + ci_l;
        const __half* bp = Xplane + (size_t)ci * PS + (y0 + br + ky) * RS + xs * 8;
        wv = *(const uint4*)bp;
        wx = *(const uint32_t*)(bp + 8);
    };
    // ---- B tile: shift into 3 kx variants, store swizzled ----
    auto stageB = [&](int buf) {
        unsigned char* Bp = sm + buf * STG + AS_B;
        const int kb = ci_l * 3;
        {
            const int k = kb;
            const int ch = (n8 & 24) | ((n8 ^ (k & 7)) & 7);
            *(uint4*)(Bp + k*512 + ch*16) = wv;
        }
        {
            const int k = kb + 1;
            const int ch = (n8 & 24) | ((n8 ^ (k & 7)) & 7);
            uint4 v;
            v.x = __funnelshift_r(wv.x, wv.y, 16);
            v.y = __funnelshift_r(wv.y, wv.z, 16);
            v.z = __funnelshift_r(wv.z, wv.w, 16);
            v.w = __funnelshift_r(wv.w, wx,   16);
            *(uint4*)(Bp + k*512 + ch*16) = v;
        }
        {
            const int k = kb + 2;
            const int ch = (n8 & 24) | ((n8 ^ (k & 7)) & 7);
            uint4 v; v.x = wv.y; v.y = wv.z; v.z = wv.w; v.w = wx;
            *(uint4*)(Bp + k*512 + ch*16) = v;
        }
    };
    // ---- mma over stage buf ----
    auto compute = [&](int buf) {
        const uint32_t aB = sbase + buf * STG;
        const uint32_t bB = aB + AS_B;
        #pragma unroll
        for (int kb = 0; kb < KT; kb += 16) {
            uint32_t af[4][4], bf[2][4];
            #pragma unroll
            for (int mi = 0; mi < 4; mi++)
                ldsm_x4(af[mi], aB + a_lane + mi*(16*A_STRIDE) + kb*2);
            ldsm_x4t(bf[0], bB + b_off0 + kb*512);
            ldsm_x4t(bf[1], bB + b_off1 + kb*512);
            #pragma unroll
            for (int mi = 0; mi < 4; mi++) {
                #pragma unroll
                for (int it = 0; it < 2; it++) {
                    mma16816(acc[mi][it*2 + 0], af[mi], bf[it][0], bf[it][1]);
                    mma16816(acc[mi][it*2 + 1], af[mi], bf[it][2], bf[it][3]);
                }
            }
        }
    };

    // prologue: stage 0 -> buf 0
    issueA(0, 0);
    gatherB(0);
    stageB(0);
    cpasync_wait0();
    __syncthreads();

    for (int t = 0; t < NSTAGE; t++) {
        if (t + 1 < NSTAGE) {
            issueA(t + 1, (t + 1) & 1);
            gatherB(t + 1);
        }
        compute(t & 1);
        if (t + 1 < NSTAGE) {
            stageB((t + 1) & 1);
            cpasync_wait0();
            __syncthreads();
        }
    }

    // fused epilogue: + noise_w*noise + bias, leaky_relu(0.2) * sqrt(2)
    const int gr = lane >> 2, tg = lane & 3;
    const float nw = noise_w[0];
    const float SQ2 = 1.4142135623730951f;
    #pragma unroll
    for (int mi = 0; mi < 4; mi++) {
        #pragma unroll
        for (int h = 0; h < 2; h++) {
            const int co = m0 + wm*64 + mi*16 + gr + 8*h;
            const float bias = act_b[co];
            const float* np = noise + (size_t)(b*COn + co) * (Hn*Hn);
            float* op = out + (size_t)(b*COn + co) * (Hn*Hn);
            #pragma unroll
            for (int ni = 0; ni < 4; ni++) {
                const int n = n0 + wn*32 + ni*8 + tg*2;
                float2 nv = *(const float2*)(np + n);
                float v0 = acc[mi][ni][2*h + 0] + nw * nv.x + bias;
                float v1 = acc[mi][ni][2*h + 1] + nw * nv.y + bias;
                float2 ov;
                ov.x = (v0 > 0.f ? v0 : 0.2f*v0) * SQ2;
                ov.y = (v1 > 0.f ? v1 : 0.2f*v1) * SQ2;
                *(float2*)(op + n) = ov;
            }
        }
    }
}

// ---------------- launch ----------------
extern "C" void kernel_launch(void* const* d_in, const int* in_sizes, int n_in,
                              void* d_out, int out_size) {
    (void)in_sizes; (void)n_in; (void)out_size;
    const float* x        = (const float*)d_in[0];  // [8,512,64,64]
    const float* style    = (const float*)d_in[1];  // [8,512]
    const float* noise    = (const float*)d_in[2];  // [8,512,64,64]
    const float* weight   = (const float*)d_in[3];  // [1,512,512,3,3]
    const float* mod_w    = (const float*)d_in[4];  // [512,512]
    const float* mod_b    = (const float*)d_in[5];  // [512]
    const float* noise_w  = (const float*)d_in[6];  // [1]
    const float* act_b    = (const float*)d_in[7];  // [512]
    float* out = (float*)d_out;

    cudaFuncSetAttribute(k_conv, cudaFuncAttributeMaxDynamicSharedMemorySize, SMEM_TOTAL);

    k_style<<<Bn, 512>>>(style, mod_w, mod_b);
    k_demod<<<Bn*COn, 256>>>(weight);
    k_wt<<<Bn*COn, 256>>>(weight);
    k_pad<<<Bn*CIn, 256>>>(x);
    dim3 gc((Hn*Hn)/TN, COn/TM, Bn);
    k_conv<<<gc, NT, SMEM_TOTAL>>>(noise, noise_w, act_b, out);
}

// round 12
// speedup vs baseline: 3.5988x; 1.0416x over previous
#include <cuda_runtime.h>
#include <cuda_fp16.h>
#include <cstdint>

#define Bn   8
#define CIn  512
#define COn  512
#define WDn  512
#define Hn   64
#define HPn  66
#define RS   72                  // padded row stride (halves), 144B = 16B aligned
#define PS   (HPn*RS)            // plane stride in halves (4752)
#define KTOT 4608
#define KP   1536                // K per ky-pass (ci*3)

// conv tiling
#define TM   128                 // co per CTA
#define TN   256                 // hw per CTA (4 image rows)
#define KT   48                  // K per stage = 16 ci x 3 kx
#define NSTAGE 96                // 3 passes x 32 stages
#define A_STRIDE 112             // 96B data + 16B pad (conflict-free ldmatrix)
#define AS_B (TM*A_STRIDE)       // 14336
#define BS_B (KT*512)            // 24576 (256 halves per k-row)
#define STG  (AS_B + BS_B)       // 38912
#define SMEM_TOTAL (2*STG)       // 77824 (dynamic)
#define NT   256                 // threads per CTA (8 warps, 2x4 grid, 64x64 warp tiles)

// ---------------- scratch (device globals; no allocations) ----------------
static __device__ float  g_s[Bn*CIn];
// weights reordered: [b][ky][co][ci*3+kx], fp16
static __device__ __align__(16) __half g_wt[(size_t)Bn*3*COn*KP];
// padded input, row stride 72: [b*CI + ci][row][72]
static __device__ __align__(16) __half g_xpad[(size_t)Bn*CIn*PS];

// ---------------- PTX helpers ----------------
__device__ __forceinline__ uint32_t smem_u32(const void* p) {
    uint32_t a;
    asm("{ .reg .u64 t; cvta.to.shared.u64 t, %1; cvt.u32.u64 %0, t; }" : "=r"(a) : "l"(p));
    return a;
}
__device__ __forceinline__ void cpasync16(uint32_t dst, const void* src) {
    asm volatile("cp.async.cg.shared.global [%0], [%1], 16;" :: "r"(dst), "l"(src));
}
__device__ __forceinline__ void cpasync_commit() {
    asm volatile("cp.async.commit_group;");
}
__device__ __forceinline__ void cpasync_wait0() {
    asm volatile("cp.async.wait_group 0;");
}
__device__ __forceinline__ void ldsm_x4(uint32_t r[4], uint32_t a) {
    asm volatile("ldmatrix.sync.aligned.m8n8.x4.shared.b16 {%0,%1,%2,%3}, [%4];"
        : "=r"(r[0]), "=r"(r[1]), "=r"(r[2]), "=r"(r[3]) : "r"(a));
}
__device__ __forceinline__ void ldsm_x4t(uint32_t r[4], uint32_t a) {
    asm volatile("ldmatrix.sync.aligned.m8n8.x4.trans.shared.b16 {%0,%1,%2,%3}, [%4];"
        : "=r"(r[0]), "=r"(r[1]), "=r"(r[2]), "=r"(r[3]) : "r"(a));
}
__device__ __forceinline__ void mma16816(float c[4], const uint32_t a[4],
                                         uint32_t b0, uint32_t b1) {
    asm volatile(
        "mma.sync.aligned.m16n8k16.row.col.f32.f16.f16.f32 "
        "{%0,%1,%2,%3},{%4,%5,%6,%7},{%8,%9},{%0,%1,%2,%3};"
        : "+f"(c[0]), "+f"(c[1]), "+f"(c[2]), "+f"(c[3])
        : "r"(a[0]), "r"(a[1]), "r"(a[2]), "r"(a[3]), "r"(b0), "r"(b1));
}

// ---------------- 1) style modulation ----------------
__global__ void k_style(const float* __restrict__ style,
                        const float* __restrict__ mw,
                        const float* __restrict__ mb) {
    const int b = blockIdx.x;
    const int ci = threadIdx.x;            // blockDim = 512
    __shared__ float st[WDn];
    st[ci] = style[b*WDn + ci];
    __syncthreads();
    const float eq = 0.044194173824159216f;  // 1/sqrt(512)
    const float* row = mw + (size_t)ci*WDn;
    float acc = 0.f;
    #pragma unroll 8
    for (int w = 0; w < WDn; w++) acc += st[w] * row[w];
    g_s[b*CIn + ci] = acc * eq + mb[ci];
}

// ---------------- 2) zero-padded fp16 input, row stride 72 ----------------
__global__ void k_pad(const float* __restrict__ x) {
    const int plane = blockIdx.x;          // b*CI + ci
    const float* src = x + (size_t)plane * (Hn*Hn);
    __half* dst = g_xpad + (size_t)plane * PS;
    for (int i = threadIdx.x; i < HPn*18; i += blockDim.x) {
        const int y = i / 18, x0 = (i - y*18) * 4;
        __half h[4];
        #pragma unroll
        for (int d = 0; d < 4; d++) {
            const int xx = x0 + d;
            float v = 0.f;
            if (y >= 1 && y <= Hn && xx >= 1 && xx <= Hn)
                v = src[(y-1)*Hn + (xx-1)];
            h[d] = __float2half_rn(v);
        }
        *(uint2*)(dst + y*RS + x0) = *(uint2*)h;
    }
}

// ---------------- 3) merged demod + modulated-weight write ----------------
// one block per (b, co): reduce sum((w*s)^2), then write fp16 [b][ky][co][ci*3+kx]
__global__ void __launch_bounds__(256) k_mod(const float* __restrict__ weight) {
    const int bc = blockIdx.x;             // b*512 + co
    const int b = bc >> 9, co = bc & 511;
    const int tid = threadIdx.x;
    __shared__ float ss[CIn];
    ss[tid] = g_s[b*CIn + tid];
    ss[tid + 256] = g_s[b*CIn + tid + 256];
    __syncthreads();

    const float* w = weight + (size_t)co*KTOT;
    float v[18];
    float acc = 0.f;
    #pragma unroll
    for (int j = 0; j < 18; j++) {
        const int i = j*256 + tid;
        v[j] = w[i] * ss[i/9];
        acc += v[j] * v[j];
    }
    #pragma unroll
    for (int o = 16; o; o >>= 1) acc += __shfl_xor_sync(0xffffffffu, acc, o);
    __shared__ float red[8];
    __shared__ float s_d;
    if ((tid & 31) == 0) red[tid >> 5] = acc;
    __syncthreads();
    if (tid == 0) {
        float t = 0.f;
        #pragma unroll
        for (int i = 0; i < 8; i++) t += red[i];
        const float cs2 = 1.0f / (float)KTOT;
        const float CS = 0.014731391274719742f;  // 1/sqrt(4608)
        s_d = rsqrtf(cs2 * t + 1e-8f) * CS;
    }
    __syncthreads();
    const float d = s_d;
    #pragma unroll
    for (int j = 0; j < 18; j++) {
        const int i = j*256 + tid;
        const int ci = i / 9, r = i - 9*ci;
        const int ky = r / 3, kx = r - 3*ky;
        g_wt[((size_t)(b*3 + ky)*COn + co)*KP + ci*3 + kx] = __float2half_rn(v[j] * d);
    }
}

// ---------------- 4) fp16 mma implicit-GEMM conv, 3 ky passes ----------------
__global__ void __launch_bounds__(NT, 1) k_conv(const float* __restrict__ noise,
                                                const float* __restrict__ noise_w,
                                                const float* __restrict__ act_b,
                                                float* __restrict__ out) {
    extern __shared__ __align__(16) unsigned char sm[];
    const uint32_t sbase = smem_u32(sm);

    const int tid = threadIdx.x, lane = tid & 31, warp = tid >> 5;
    const int wm = warp & 1, wn = warp >> 1;        // 2 x 4 warp grid, 64x64 tiles
    const int n0 = blockIdx.x * TN;                 // hw tile (4 image rows)
    const int m0 = blockIdx.y * TM;                 // co tile
    const int b  = blockIdx.z;
    const int y0 = n0 >> 6;                         // first image row

    // A cp.async map: 768 chunks of 16B -> 3 per thread
    // B g2s map: 512 slots (16 ci x 4 rows x 8 xs) -> 2 per thread
    const int s0 = tid;                             // B slot 0
    const int ci0 = s0 >> 5;
    const int br = (s0 >> 3) & 3;
    const int xs = s0 & 7;
    const int n8 = br * 8 + xs;                     // n-chunk 0..31 (same for both slots)

    // ldmatrix per-lane offsets
    const uint32_t a_lane = (uint32_t)((wm*64 + (lane & 15)) * A_STRIDE + (lane >> 4) * 16);
    const int krow0 = lane & 15;
    const int bc0 = wn * 8 + (lane >> 4);
    uint32_t b_off[4];
    #pragma unroll
    for (int j = 0; j < 4; j++) {
        const int c = bc0 + 2*j;
        const int sw = (c & 24) | ((c ^ (krow0 & 7)) & 7);
        b_off[j] = (uint32_t)(krow0 * 512 + sw * 16);
    }

    float acc[4][8][4];
    #pragma unroll
    for (int i = 0; i < 4; i++)
        #pragma unroll
        for (int j = 0; j < 8; j++)
            #pragma unroll
            for (int q = 0; q < 4; q++) acc[i][j][q] = 0.f;

    uint4 wv0, wv1;
    uint32_t wx0, wx1;

    const __half* Xplane = g_xpad + (size_t)b * CIn * PS;

    // ---- A tile: issue cp.async for stage t into buf ----
    auto issueA = [&](int t, int buf) {
        const int ky = t >> 5;
        const int k0 = (t & 31) * KT;
        const char* src = (const char*)(g_wt + ((size_t)(b*3 + ky)*COn + m0) * KP + k0);
        const uint32_t dst = sbase + buf * STG;
        #pragma unroll
        for (int i = 0; i < 3; i++) {
            const int c = tid + i*NT;
            const int r = c / 6, o = (c - 6*r) * 16;
            cpasync16(dst + r*A_STRIDE + o, src + (size_t)r*(KP*2) + o);
        }
        cpasync_commit();
    };
    // ---- B tile: gather raw row segments into registers (2 slots) ----
    auto gatherB = [&](int t) {
        const int ky = t >> 5;
        const int k0 = (t & 31) * KT;
        const int cib = (k0 / 3);
        const __half* bp0 = Xplane + (size_t)(cib + ci0) * PS + (y0 + br + ky) * RS + xs * 8;
        const __half* bp1 = bp0 + (size_t)8 * PS;   // second slot: ci0 + 8
        wv0 = *(const uint4*)bp0;
        wx0 = *(const uint32_t*)(bp0 + 8);
        wv1 = *(const uint4*)bp1;
        wx1 = *(const uint32_t*)(bp1 + 8);
    };
    // ---- B tile: shift into 3 kx variants, store swizzled ----
    auto stageB = [&](int buf) {
        unsigned char* Bp = sm + buf * STG + AS_B;
        #pragma unroll
        for (int sl = 0; sl < 2; sl++) {
            const uint4 wv = sl ? wv1 : wv0;
            const uint32_t wx = sl ? wx1 : wx0;
            const int kb = (ci0 + sl*8) * 3;
            {
                const int k = kb;
                const int ch = (n8 & 24) | ((n8 ^ (k & 7)) & 7);
                *(uint4*)(Bp + k*512 + ch*16) = wv;
            }
            {
                const int k = kb + 1;
                const int ch = (n8 & 24) | ((n8 ^ (k & 7)) & 7);
                uint4 v;
                v.x = __funnelshift_r(wv.x, wv.y, 16);
                v.y = __funnelshift_r(wv.y, wv.z, 16);
                v.z = __funnelshift_r(wv.z, wv.w, 16);
                v.w = __funnelshift_r(wv.w, wx,   16);
                *(uint4*)(Bp + k*512 + ch*16) = v;
            }
            {
                const int k = kb + 2;
                const int ch = (n8 & 24) | ((n8 ^ (k & 7)) & 7);
                uint4 v; v.x = wv.y; v.y = wv.z; v.z = wv.w; v.w = wx;
                *(uint4*)(Bp + k*512 + ch*16) = v;
            }
        }
    };
    // ---- mma over stage buf: 64x64 warp tile ----
    auto compute = [&](int buf) {
        const uint32_t aB = sbase + buf * STG;
        const uint32_t bB = aB + AS_B;
        #pragma unroll
        for (int kb = 0; kb < KT; kb += 16) {
            uint32_t af[4][4], bf[4][4];
            #pragma unroll
            for (int mi = 0; mi < 4; mi++)
                ldsm_x4(af[mi], aB + a_lane + mi*(16*A_STRIDE) + kb*2);
            #pragma unroll
            for (int jt = 0; jt < 4; jt++)
                ldsm_x4t(bf[jt], bB + b_off[jt] + kb*512);
            #pragma unroll
            for (int mi = 0; mi < 4; mi++) {
                #pragma unroll
                for (int jt = 0; jt < 4; jt++) {
                    mma16816(acc[mi][jt*2 + 0], af[mi], bf[jt][0], bf[jt][1]);
                    mma16816(acc[mi][jt*2 + 1], af[mi], bf[jt][2], bf[jt][3]);
                }
            }
        }
    };

    // prologue: stage 0 -> buf 0
    issueA(0, 0);
    gatherB(0);
    stageB(0);
    cpasync_wait0();
    __syncthreads();

    for (int t = 0; t < NSTAGE; t++) {
        if (t + 1 < NSTAGE) {
            issueA(t + 1, (t + 1) & 1);
            gatherB(t + 1);
        }
        compute(t & 1);
        if (t + 1 < NSTAGE) {
            stageB((t + 1) & 1);
            cpasync_wait0();
            __syncthreads();
        }
    }

    // fused epilogue: + noise_w*noise + bias, leaky_relu(0.2) * sqrt(2)
    const int gr = lane >> 2, tg = lane & 3;
    const float nw = noise_w[0];
    const float SQ2 = 1.4142135623730951f;
    #pragma unroll
    for (int mi = 0; mi < 4; mi++) {
        #pragma unroll
        for (int h = 0; h < 2; h++) {
            const int co = m0 + wm*64 + mi*16 + gr + 8*h;
            const float bias = act_b[co];
            const float* np = noise + (size_t)(b*COn + co) * (Hn*Hn);
            float* op = out + (size_t)(b*COn + co) * (Hn*Hn);
            #pragma unroll
            for (int ni = 0; ni < 8; ni++) {
                const int n = n0 + wn*64 + ni*8 + tg*2;
                float2 nv = *(const float2*)(np + n);
                float v0 = acc[mi][ni][2*h + 0] + nw * nv.x + bias;
                float v1 = acc[mi][ni][2*h + 1] + nw * nv.y + bias;
                float2 ov;
                ov.x = (v0 > 0.f ? v0 : 0.2f*v0) * SQ2;
                ov.y = (v1 > 0.f ? v1 : 0.2f*v1) * SQ2;
                *(float2*)(op + n) = ov;
            }
        }
    }
}

// ---------------- launch ----------------
extern "C" void kernel_launch(void* const* d_in, const int* in_sizes, int n_in,
                              void* d_out, int out_size) {
    (void)in_sizes; (void)n_in; (void)out_size;
    const float* x        = (const float*)d_in[0];  // [8,512,64,64]
    const float* style    = (const float*)d_in[1];  // [8,512]
    const float* noise    = (const float*)d_in[2];  // [8,512,64,64]
    const float* weight   = (const float*)d_in[3];  // [1,512,512,3,3]
    const float* mod_w    = (const float*)d_in[4];  // [512,512]
    const float* mod_b    = (const float*)d_in[5];  // [512]
    const float* noise_w  = (const float*)d_in[6];  // [1]
    const float* act_b    = (const float*)d_in[7];  // [512]
    float* out = (float*)d_out;

    cudaFuncSetAttribute(k_conv, cudaFuncAttributeMaxDynamicSharedMemorySize, SMEM_TOTAL);

    k_style<<<Bn, 512>>>(style, mod_w, mod_b);
    k_pad<<<Bn*CIn, 256>>>(x);
    k_mod<<<Bn*COn, 256>>>(weight);
    dim3 gc((Hn*Hn)/TN, COn/TM, Bn);
    k_conv<<<gc, NT, SMEM_TOTAL>>>(noise, noise_w, act_b, out);
}

// round 13
// speedup vs baseline: 5.0286x; 1.3973x over previous
#include <cuda_runtime.h>
#include <cuda_fp16.h>
#include <cstdint>

#define Bn   8
#define CIn  512
#define COn  512
#define WDn  512
#define Hn   64
#define HPn  66
#define RS   72                  // padded row stride (halves), 144B = 16B aligned
#define PS   (HPn*RS)            // plane stride in halves (4752)
#define KTOT 4608
#define KP   1536                // K per ky-pass (ci*3)

// conv tiling (R7-proven geometry + occ-2)
#define TM   128                 // co per CTA
#define TN   128                 // hw per CTA (2 image rows)
#define KT   48                  // K per stage = 16 ci x 3 kx
#define NSTAGE 96                // 3 passes x 32 stages
#define A_STRIDE 112             // 96B data + 16B pad (conflict-free ldmatrix)
#define AS_B (TM*A_STRIDE)       // 14336
#define BS_B (KT*256)            // 12288 (128 halves per k-row)
#define STG  (AS_B + BS_B)       // 26624
#define SMEM_TOTAL (2*STG)       // 53248 (dynamic); x2 CTAs = 106.5 KB/SM
#define NT   256                 // threads per CTA (8 warps, 2x4, 64x32 warp tiles)

// ---------------- scratch (device globals; no allocations) ----------------
static __device__ float  g_s[Bn*CIn];
// weights reordered: [b][ky][co][ci*3+kx], fp16
static __device__ __align__(16) __half g_wt[(size_t)Bn*3*COn*KP];
// padded input, row stride 72: [b*CI + ci][row][72]
static __device__ __align__(16) __half g_xpad[(size_t)Bn*CIn*PS];

// ---------------- PTX helpers ----------------
__device__ __forceinline__ uint32_t smem_u32(const void* p) {
    uint32_t a;
    asm("{ .reg .u64 t; cvta.to.shared.u64 t, %1; cvt.u32.u64 %0, t; }" : "=r"(a) : "l"(p));
    return a;
}
__device__ __forceinline__ void cpasync16(uint32_t dst, const void* src) {
    asm volatile("cp.async.cg.shared.global [%0], [%1], 16;" :: "r"(dst), "l"(src));
}
__device__ __forceinline__ void cpasync_commit() {
    asm volatile("cp.async.commit_group;");
}
__device__ __forceinline__ void cpasync_wait0() {
    asm volatile("cp.async.wait_group 0;");
}
__device__ __forceinline__ void ldsm_x4(uint32_t r[4], uint32_t a) {
    asm volatile("ldmatrix.sync.aligned.m8n8.x4.shared.b16 {%0,%1,%2,%3}, [%4];"
        : "=r"(r[0]), "=r"(r[1]), "=r"(r[2]), "=r"(r[3]) : "r"(a));
}
__device__ __forceinline__ void ldsm_x4t(uint32_t r[4], uint32_t a) {
    asm volatile("ldmatrix.sync.aligned.m8n8.x4.trans.shared.b16 {%0,%1,%2,%3}, [%4];"
        : "=r"(r[0]), "=r"(r[1]), "=r"(r[2]), "=r"(r[3]) : "r"(a));
}
__device__ __forceinline__ void mma16816(float c[4], const uint32_t a[4],
                                         uint32_t b0, uint32_t b1) {
    asm volatile(
        "mma.sync.aligned.m16n8k16.row.col.f32.f16.f16.f32 "
        "{%0,%1,%2,%3},{%4,%5,%6,%7},{%8,%9},{%0,%1,%2,%3};"
        : "+f"(c[0]), "+f"(c[1]), "+f"(c[2]), "+f"(c[3])
        : "r"(a[0]), "r"(a[1]), "r"(a[2]), "r"(a[3]), "r"(b0), "r"(b1));
}

// ---------------- 1) style modulation (64 blocks of 64 ci rows) ----------------
__global__ void __launch_bounds__(256) k_style(const float* __restrict__ style,
                                               const float* __restrict__ mw,
                                               const float* __restrict__ mb) {
    const int b = blockIdx.x >> 3;         // 8 groups per batch
    const int g = blockIdx.x & 7;
    const int tid = threadIdx.x;
    const int ci_l = tid >> 2;             // 64 ci rows per block
    const int q = tid & 3;                 // quarter of 512
    __shared__ float st[WDn];
    st[tid] = style[b*WDn + tid];
    st[tid + 256] = style[b*WDn + tid + 256];
    __syncthreads();
    const int ci = g*64 + ci_l;
    const float* row = mw + (size_t)ci*WDn + q*128;
    const float* sv = st + q*128;
    float acc = 0.f;
    #pragma unroll 16
    for (int w = 0; w < 128; w++) acc += sv[w] * row[w];
    acc += __shfl_xor_sync(0xffffffffu, acc, 1);
    acc += __shfl_xor_sync(0xffffffffu, acc, 2);
    if (q == 0) {
        const float eq = 0.044194173824159216f;  // 1/sqrt(512)
        g_s[b*CIn + ci] = acc * eq + mb[ci];
    }
}

// ---------------- 2) zero-padded fp16 input, row stride 72 ----------------
__global__ void k_pad(const float* __restrict__ x) {
    const int plane = blockIdx.x;          // b*CI + ci
    const float* src = x + (size_t)plane * (Hn*Hn);
    __half* dst = g_xpad + (size_t)plane * PS;
    for (int i = threadIdx.x; i < HPn*18; i += blockDim.x) {
        const int y = i / 18, x0 = (i - y*18) * 4;
        __half h[4];
        #pragma unroll
        for (int d = 0; d < 4; d++) {
            const int xx = x0 + d;
            float v = 0.f;
            if (y >= 1 && y <= Hn && xx >= 1 && xx <= Hn)
                v = src[(y-1)*Hn + (xx-1)];
            h[d] = __float2half_rn(v);
        }
        *(uint2*)(dst + y*RS + x0) = *(uint2*)h;
    }
}

// ---------------- 3) merged demod + modulated-weight write ----------------
__global__ void __launch_bounds__(256) k_mod(const float* __restrict__ weight) {
    const int bc = blockIdx.x;             // b*512 + co
    const int b = bc >> 9, co = bc & 511;
    const int tid = threadIdx.x;
    __shared__ float ss[CIn];
    ss[tid] = g_s[b*CIn + tid];
    ss[tid + 256] = g_s[b*CIn + tid + 256];
    __syncthreads();

    const float* w = weight + (size_t)co*KTOT;
    float v[18];
    float acc = 0.f;
    #pragma unroll
    for (int j = 0; j < 18; j++) {
        const int i = j*256 + tid;
        v[j] = w[i] * ss[i/9];
        acc += v[j] * v[j];
    }
    #pragma unroll
    for (int o = 16; o; o >>= 1) acc += __shfl_xor_sync(0xffffffffu, acc, o);
    __shared__ float red[8];
    __shared__ float s_d;
    if ((tid & 31) == 0) red[tid >> 5] = acc;
    __syncthreads();
    if (tid == 0) {
        float t = 0.f;
        #pragma unroll
        for (int i = 0; i < 8; i++) t += red[i];
        const float cs2 = 1.0f / (float)KTOT;
        const float CS = 0.014731391274719742f;  // 1/sqrt(4608)
        s_d = rsqrtf(cs2 * t + 1e-8f) * CS;
    }
    __syncthreads();
    const float d = s_d;
    #pragma unroll
    for (int j = 0; j < 18; j++) {
        const int i = j*256 + tid;
        const int ci = i / 9, r = i - 9*ci;
        const int ky = r / 3, kx = r - 3*ky;
        g_wt[((size_t)(b*3 + ky)*COn + co)*KP + ci*3 + kx] = __float2half_rn(v[j] * d);
    }
}

// ---------------- 4) fp16 mma implicit-GEMM conv, 3 ky passes, occ 2 ----------------
__global__ void __launch_bounds__(NT, 2) k_conv(const float* __restrict__ noise,
                                                const float* __restrict__ noise_w,
                                                const float* __restrict__ act_b,
                                                float* __restrict__ out) {
    extern __shared__ __align__(16) unsigned char sm[];
    const uint32_t sbase = smem_u32(sm);

    const int tid = threadIdx.x, lane = tid & 31, warp = tid >> 5;
    const int wm = warp & 1, wn = warp >> 1;        // 2 x 4 warp grid, 64x32 tiles
    const int n0 = blockIdx.x * TN;                 // hw tile (2 image rows)
    const int m0 = blockIdx.y * TM;                 // co tile
    const int b  = blockIdx.z;
    const int y0 = n0 >> 6;                         // first image row

    // B g2s map: 256 slots = 16 ci x 2 rows x 8 xs -> 1 per thread
    const int ci_l = tid >> 4;
    const int br = (tid >> 3) & 1;
    const int xs = tid & 7;
    const int n8 = br * 8 + xs;                     // n-chunk 0..15

    // ldmatrix per-lane offsets
    const uint32_t a_lane = (uint32_t)((wm*64 + (lane & 15)) * A_STRIDE + (lane >> 4) * 16);
    const int krow0 = lane & 15;
    const int bc0 = wn * 4 + (lane >> 4);
    const uint32_t b_off0 = (uint32_t)(krow0 * 256 + (((bc0 + 0) ^ (krow0 & 7)) & 15) * 16
                                       + ((bc0 + 0) & 8) * 0);
    const uint32_t b_off1 = (uint32_t)(krow0 * 256 + (((bc0 + 2) ^ (krow0 & 7)) & 15) * 16);
    // note: bc0 <= 15 and (krow0&7) <= 7 so XOR preserves bit 3 automatically

    float acc[4][4][4];
    #pragma unroll
    for (int i = 0; i < 4; i++)
        #pragma unroll
        for (int j = 0; j < 4; j++)
            #pragma unroll
            for (int q = 0; q < 4; q++) acc[i][j][q] = 0.f;

    uint4 wv;
    uint32_t wx;

    const __half* Xplane = g_xpad + (size_t)b * CIn * PS;

    // ---- A tile: cp.async, 768 chunks of 16B -> 3 per thread ----
    auto issueA = [&](int t, int buf) {
        const int ky = t >> 5;
        const int k0 = (t & 31) * KT;
        const char* src = (const char*)(g_wt + ((size_t)(b*3 + ky)*COn + m0) * KP + k0);
        const uint32_t dst = sbase + buf * STG;
        #pragma unroll
        for (int i = 0; i < 3; i++) {
            const int c = tid + i*NT;
            const int r = c / 6, o = (c - 6*r) * 16;
            cpasync16(dst + r*A_STRIDE + o, src + (size_t)r*(KP*2) + o);
        }
        cpasync_commit();
    };
    // ---- B tile: gather raw row segment into registers ----
    auto gatherB = [&](int t) {
        const int ky = t >> 5;
        const int k0 = (t & 31) * KT;
        const int ci = (k0 / 3) + ci_l;
        const __half* bp = Xplane + (size_t)ci * PS + (y0 + br + ky) * RS + xs * 8;
        wv = *(const uint4*)bp;
        wx = *(const uint32_t*)(bp + 8);
    };
    // ---- B tile: shift into 3 kx variants, store swizzled ----
    auto stageB = [&](int buf) {
        unsigned char* Bp = sm + buf * STG + AS_B;
        const int kb = ci_l * 3;
        {
            const int k = kb;
            *(uint4*)(Bp + k*256 + ((n8 ^ (k & 7)) * 16)) = wv;
        }
        {
            const int k = kb + 1;
            uint4 v;
            v.x = __funnelshift_r(wv.x, wv.y, 16);
            v.y = __funnelshift_r(wv.y, wv.z, 16);
            v.z = __funnelshift_r(wv.z, wv.w, 16);
            v.w = __funnelshift_r(wv.w, wx,   16);
            *(uint4*)(Bp + k*256 + ((n8 ^ (k & 7)) * 16)) = v;
        }
        {
            const int k = kb + 2;
            uint4 v; v.x = wv.y; v.y = wv.z; v.z = wv.w; v.w = wx;
            *(uint4*)(Bp + k*256 + ((n8 ^ (k & 7)) * 16)) = v;
        }
    };
    // ---- mma over stage buf: 64x32 warp tile ----
    auto compute = [&](int buf) {
        const uint32_t aB = sbase + buf * STG;
        const uint32_t bB = aB + AS_B;
        #pragma unroll
        for (int kb = 0; kb < KT; kb += 16) {
            uint32_t af[4][4], bf[2][4];
            #pragma unroll
            for (int mi = 0; mi < 4; mi++)
                ldsm_x4(af[mi], aB + a_lane + mi*(16*A_STRIDE) + kb*2);
            ldsm_x4t(bf[0], bB + b_off0 + kb*256);
            ldsm_x4t(bf[1], bB + b_off1 + kb*256);
            #pragma unroll
            for (int mi = 0; mi < 4; mi++) {
                #pragma unroll
                for (int it = 0; it < 2; it++) {
                    mma16816(acc[mi][it*2 + 0], af[mi], bf[it][0], bf[it][1]);
                    mma16816(acc[mi][it*2 + 1], af[mi], bf[it][2], bf[it][3]);
                }
            }
        }
    };

    // prologue: stage 0 -> buf 0
    issueA(0, 0);
    gatherB(0);
    stageB(0);
    cpasync_wait0();
    __syncthreads();

    for (int t = 0; t < NSTAGE; t++) {
        if (t + 1 < NSTAGE) {
            issueA(t + 1, (t + 1) & 1);
            gatherB(t + 1);
        }
        compute(t & 1);
        if (t + 1 < NSTAGE) {
            stageB((t + 1) & 1);
            cpasync_wait0();
            __syncthreads();
        }
    }

    // fused epilogue: + noise_w*noise + bias, leaky_relu(0.2) * sqrt(2)
    const int gr = lane >> 2, tg = lane & 3;
    const float nw = noise_w[0];
    const float SQ2 = 1.4142135623730951f;
    #pragma unroll
    for (int mi = 0; mi < 4; mi++) {
        #pragma unroll
        for (int h = 0; h < 2; h++) {
            const int co = m0 + wm*64 + mi*16 + gr + 8*h;
            const float bias = act_b[co];
            const float* np = noise + (size_t)(b*COn + co) * (Hn*Hn);
            float* op = out + (size_t)(b*COn + co) * (Hn*Hn);
            #pragma unroll
            for (int ni = 0; ni < 4; ni++) {
                const int n = n0 + wn*32 + ni*8 + tg*2;
                float2 nv = *(const float2*)(np + n);
                float v0 = acc[mi][ni][2*h + 0] + nw * nv.x + bias;
                float v1 = acc[mi][ni][2*h + 1] + nw * nv.y + bias;
                float2 ov;
                ov.x = (v0 > 0.f ? v0 : 0.2f*v0) * SQ2;
                ov.y = (v1 > 0.f ? v1 : 0.2f*v1) * SQ2;
                *(float2*)(op + n) = ov;
            }
        }
    }
}

// ---------------- launch ----------------
extern "C" void kernel_launch(void* const* d_in, const int* in_sizes, int n_in,
                              void* d_out, int out_size) {
    (void)in_sizes; (void)n_in; (void)out_size;
    const float* x        = (const float*)d_in[0];  // [8,512,64,64]
    const float* style    = (const float*)d_in[1];  // [8,512]
    const float* noise    = (const float*)d_in[2];  // [8,512,64,64]
    const float* weight   = (const float*)d_in[3];  // [1,512,512,3,3]
    const float* mod_w    = (const float*)d_in[4];  // [512,512]
    const float* mod_b    = (const float*)d_in[5];  // [512]
    const float* noise_w  = (const float*)d_in[6];  // [1]
    const float* act_b    = (const float*)d_in[7];  // [512]
    float* out = (float*)d_out;

    cudaFuncSetAttribute(k_conv, cudaFuncAttributeMaxDynamicSharedMemorySize, SMEM_TOTAL);

    k_style<<<Bn*8, 256>>>(style, mod_w, mod_b);
    k_pad<<<Bn*CIn, 256>>>(x);
    k_mod<<<Bn*COn, 256>>>(weight);
    dim3 gc((Hn*Hn)/TN, COn/TM, Bn);
    k_conv<<<gc, NT, SMEM_TOTAL>>>(noise, noise_w, act_b, out);
}